// round 11
// baseline (speedup 1.0000x reference)
#include <cuda_runtime.h>
#include <cuda_fp16.h>
#include <mma.h>
#include <cstdint>

using namespace nvcuda;

#define NN 100000
#define NE 600000
#define D  128
#define CAP 64

// ---------------- device scratch ----------------
__device__ int    g_cnt[NN];
__device__ uint2  g_bucket[(size_t)NN * CAP];   // (src, weight_bits)
__device__ __half g_wt[2 * D * D];              // fp16 [Wl ; Wr]  (K-row major [256][128])

__device__ __forceinline__ uint32_t h2_bits(__half2 h) {
    uint32_t u;
    *(__half2*)&u = h;
    return u;
}

// ---------------- cp.async helpers ----------------
__device__ __forceinline__ void cp_async16(uint32_t dst, const void* src) {
    asm volatile("cp.async.cg.shared.global [%0], [%1], 16;"
                 :: "r"(dst), "l"(src) : "memory");
}
#define CP_COMMIT() asm volatile("cp.async.commit_group;" ::: "memory")
#define CP_WAIT(n)  asm volatile("cp.async.wait_group %0;" :: "n"(n) : "memory")

// ---------------- prep: zero counters + convert weights to fp16 ----------------
__global__ void __launch_bounds__(256) prep_kernel(
    const float* __restrict__ wl, const float* __restrict__ wr)
{
    int i = blockIdx.x * 256 + threadIdx.x;
    if (i < NN) g_cnt[i] = 0;
    if (i < D * D) {
        g_wt[i]         = __float2half_rn(wl[i]);
        g_wt[D * D + i] = __float2half_rn(wr[i]);
    }
}

// ---------------- scatter edges into buckets ----------------
__global__ void __launch_bounds__(256) scatter_kernel(
    const int* __restrict__ esrc,
    const int* __restrict__ edst,
    const float* __restrict__ ew)
{
    int e = blockIdx.x * 256 + threadIdx.x;
    if (e >= NE) return;
    int s = __ldg(&esrc[e]);
    int d = __ldg(&edst[e]);
    float w = __ldg(&ew[e]);
    int pos = atomicAdd(&g_cnt[d], 1);
    g_bucket[(size_t)d * CAP + pos] = make_uint2((unsigned)s, __float_as_uint(w));
}

// ---------------- fused gather + dual fp16 GEMM (B smem-resident) -------------
// out[tile] = agg(tile) @ Wl + x(tile) @ Wr + (bl+br)
#define BM 128
#define LDA 136     // halves
#define LDB 136     // halves
#define LDBI 136    // floats

// smem byte offsets
#define OFF_AS   0
#define OFF_B    (BM * LDA * 2)                      // 34816
#define OFF_BIAS (OFF_B + 256 * LDB * 2)             // +69632 = 104448
#define SM_BYTES (OFF_BIAS + 16 * LDBI * 4)          // +8704  = 113152

__global__ void __launch_bounds__(256, 2) fused_kernel(
    const float* __restrict__ x,
    const float* __restrict__ bl,
    const float* __restrict__ br,
    float* __restrict__ out)
{
    extern __shared__ char smraw[];
    __half (*As)[LDA] = (__half(*)[LDA])(smraw + OFF_AS);
    __half* Bsm  = (__half*)(smraw + OFF_B);     // [256][LDB]
    float*  Bias = (float*) (smraw + OFF_BIAS);  // [16][LDBI]

    const int tid = threadIdx.x;
    const int wid = tid >> 5;
    const int lane = tid & 31;
    const int warp_m = wid & 3;    // 32-row group
    const int warp_n = wid >> 2;   // 64-col group
    const int m0 = blockIdx.x * BM;

    // ---- issue the ENTIRE B load (64KB); gather hides it ----
    {
        uint32_t b_base = (uint32_t)__cvta_generic_to_shared(Bsm);
        const int c8 = (tid & 15) * 8;
        const int r0 = tid >> 4;
        #pragma unroll
        for (int it = 0; it < 16; it++) {
            int row = r0 + it * 16;
            cp_async16(b_base + (row * LDB + c8) * 2,
                       &g_wt[(size_t)row * D + c8]);
        }
        CP_COMMIT();
    }

    // ---- bias replica tile (fp32) ----
    for (int s = tid; s < 16 * LDBI; s += 256) {
        int c = s % LDBI;
        Bias[s] = (c < 128) ? (bl[c] + br[c]) : 0.f;
    }

    // ---- phase 1: gather, 4-node interleaved; stash x rows as fp16 in regs ----
    uint2 xs[16];   // per-lane fp16 x stash: row i -> 4 halves at col lane*4
    {
        const int base_row = wid * 16;
        #pragma unroll
        for (int g = 0; g < 4; g++) {
            float4 acc[4];
            float4 xv[4];
            int    deg[4];
            const uint2* bk[4];
            #pragma unroll
            for (int q = 0; q < 4; q++) {
                int n = m0 + base_row + g * 4 + q;
                acc[q] = make_float4(0.f, 0.f, 0.f, 0.f);
                xv[q]  = make_float4(0.f, 0.f, 0.f, 0.f);
                deg[q] = 0;
                bk[q]  = &g_bucket[0];
                if (n < NN) {
                    deg[q] = __ldg(&g_cnt[n]);
                    bk[q]  = &g_bucket[(size_t)n * CAP];
                    xv[q]  = *(const float4*)&x[(size_t)n * D + lane * 4];
                }
            }
            int mx = max(max(deg[0], deg[1]), max(deg[2], deg[3]));
            for (int j = 0; j < mx; j++) {
                uint2 e[4];
                #pragma unroll
                for (int q = 0; q < 4; q++)
                    if (j < deg[q]) e[q] = __ldg(&bk[q][j]);
                #pragma unroll
                for (int q = 0; q < 4; q++) {
                    if (j < deg[q]) {
                        float w = __uint_as_float(e[q].y);
                        float4 v = *(const float4*)&x[(size_t)e[q].x * D + lane * 4];
                        acc[q].x += w * v.x; acc[q].y += w * v.y;
                        acc[q].z += w * v.z; acc[q].w += w * v.w;
                    }
                }
            }
            #pragma unroll
            for (int q = 0; q < 4; q++) {
                int row = base_row + g * 4 + q;
                __half2* da = (__half2*)&As[row][lane * 4];
                da[0] = __floats2half2_rn(acc[q].x, acc[q].y);
                da[1] = __floats2half2_rn(acc[q].z, acc[q].w);
                __half2 h0 = __floats2half2_rn(xv[q].x, xv[q].y);
                __half2 h1 = __floats2half2_rn(xv[q].z, xv[q].w);
                xs[g * 4 + q] = make_uint2(h2_bits(h0), h2_bits(h1));
            }
        }
    }
    CP_WAIT(0);
    __syncthreads();

    // ---- init accumulators from bias ----
    wmma::fragment<wmma::accumulator, 16, 16, 16, float> acc[2][4];
    #pragma unroll
    for (int i = 0; i < 2; i++)
        #pragma unroll
        for (int j = 0; j < 4; j++)
            wmma::load_matrix_sync(acc[i][j], &Bias[warp_n * 64 + j * 16], LDBI,
                                   wmma::mem_row_major);

    // ---- GEMM over one K-half: no barriers, no waits ----
    auto gemm_half = [&](int kbase) {
        #pragma unroll
        for (int kc = 0; kc < 8; kc++) {
            wmma::fragment<wmma::matrix_a, 16, 16, 16, __half, wmma::row_major> af[2];
            #pragma unroll
            for (int i = 0; i < 2; i++)
                wmma::load_matrix_sync(af[i], &As[warp_m * 32 + i * 16][kc * 16], LDA);
            #pragma unroll
            for (int j = 0; j < 4; j++) {
                wmma::fragment<wmma::matrix_b, 16, 16, 16, __half, wmma::row_major> bf;
                wmma::load_matrix_sync(bf,
                    &Bsm[(size_t)(kbase + kc * 16) * LDB + warp_n * 64 + j * 16], LDB);
                #pragma unroll
                for (int i = 0; i < 2; i++)
                    wmma::mma_sync(acc[i][j], af[i], bf, acc[i][j]);
            }
        }
    };

    // ---- phase 2: agg @ Wl ----
    gemm_half(0);

    // ---- phase 3: write stashed x rows into As (register -> smem, no global) ----
    __syncthreads();
    {
        const int base_row = wid * 16;
        #pragma unroll
        for (int i = 0; i < 16; i++)
            *(uint2*)&As[base_row + i][lane * 4] = xs[i];
    }
    __syncthreads();

    // ---- phase 4: x @ Wr ----
    gemm_half(128);

    // ---- epilogue (NN % 16 == 0 -> tiles fully in or out) ----
    #pragma unroll
    for (int i = 0; i < 2; i++) {
        int row0 = m0 + warp_m * 32 + i * 16;
        if (row0 >= NN) continue;
        #pragma unroll
        for (int j = 0; j < 4; j++) {
            int col0 = warp_n * 64 + j * 16;
            wmma::store_matrix_sync(&out[(size_t)row0 * D + col0], acc[i][j], D,
                                    wmma::mem_row_major);
        }
    }
}

// ---------------- launch ----------------
extern "C" void kernel_launch(void* const* d_in, const int* in_sizes, int n_in,
                              void* d_out, int out_size)
{
    const float* x    = (const float*)d_in[0];
    const int*   esrc = (const int*)  d_in[1];
    const int*   edst = (const int*)  d_in[2];
    const float* ew   = (const float*)d_in[3];
    const float* wl   = (const float*)d_in[4];
    const float* bl   = (const float*)d_in[5];
    const float* wr   = (const float*)d_in[6];
    const float* br   = (const float*)d_in[7];
    float* out = (float*)d_out;

    static bool attr_set = false;
    if (!attr_set) {
        cudaFuncSetAttribute(fused_kernel,
                             cudaFuncAttributeMaxDynamicSharedMemorySize, SM_BYTES);
        attr_set = true;
    }

    prep_kernel<<<(NN + 255) / 256, 256>>>(wl, wr);
    scatter_kernel<<<(NE + 255) / 256, 256>>>(esrc, edst, ew);
    fused_kernel<<<(NN + BM - 1) / BM, 256, SM_BYTES>>>(x, bl, br, out);
}

// round 12
// speedup vs baseline: 1.0113x; 1.0113x over previous
#include <cuda_runtime.h>
#include <cuda_fp16.h>
#include <mma.h>
#include <cstdint>

using namespace nvcuda;

#define NN 100000
#define NE 600000
#define D  128
#define CAP 64

// ---------------- device scratch ----------------
__device__ int    g_cnt[NN];                    // zero-init; self-cleaned by fused_kernel
__device__ uint2  g_bucket[(size_t)NN * CAP];   // (src, weight_bits)
__device__ __half g_wt[2 * D * D];              // fp16 [Wl ; Wr]  (K-row major [256][128])

// ---------------- cp.async helpers ----------------
__device__ __forceinline__ void cp_async16(uint32_t dst, const void* src) {
    asm volatile("cp.async.cg.shared.global [%0], [%1], 16;"
                 :: "r"(dst), "l"(src) : "memory");
}
#define CP_COMMIT() asm volatile("cp.async.commit_group;" ::: "memory")
#define CP_WAIT(n)  asm volatile("cp.async.wait_group %0;" :: "n"(n) : "memory")

// ---------------- prep: convert weights to fp16 (64 blocks exactly) ----------
__global__ void __launch_bounds__(256) prep_kernel(
    const float* __restrict__ wl, const float* __restrict__ wr)
{
    int i = blockIdx.x * 256 + threadIdx.x;   // 0..16383 = D*D
    g_wt[i]         = __float2half_rn(wl[i]);
    g_wt[D * D + i] = __float2half_rn(wr[i]);
}

// ---------------- scatter edges into buckets ----------------
__global__ void __launch_bounds__(256) scatter_kernel(
    const int* __restrict__ esrc,
    const int* __restrict__ edst,
    const float* __restrict__ ew)
{
    int e = blockIdx.x * 256 + threadIdx.x;
    if (e >= NE) return;
    int s = __ldg(&esrc[e]);
    int d = __ldg(&edst[e]);
    float w = __ldg(&ew[e]);
    int pos = atomicAdd(&g_cnt[d], 1);
    g_bucket[(size_t)d * CAP + pos] = make_uint2((unsigned)s, __float_as_uint(w));
}

// ---------------- fused gather + dual fp16 GEMM (B smem-resident) -------------
// out[tile] = agg(tile) @ Wl + x(tile) @ Wr + (bl+br)
#define BM 128
#define LDA 136     // halves
#define LDB 136     // halves
#define LDBI 136    // floats

// smem byte offsets
#define OFF_AS   0
#define OFF_B    (BM * LDA * 2)                      // 34816
#define OFF_BIAS (OFF_B + 256 * LDB * 2)             // +69632 = 104448
#define SM_BYTES (OFF_BIAS + 16 * LDBI * 4)          // +8704  = 113152

__global__ void __launch_bounds__(256, 2) fused_kernel(
    const float* __restrict__ x,
    const float* __restrict__ bl,
    const float* __restrict__ br,
    float* __restrict__ out)
{
    extern __shared__ char smraw[];
    __half (*As)[LDA] = (__half(*)[LDA])(smraw + OFF_AS);
    __half* Bsm  = (__half*)(smraw + OFF_B);     // [256][LDB]
    float*  Bias = (float*) (smraw + OFF_BIAS);  // [16][LDBI]

    const int tid = threadIdx.x;
    const int wid = tid >> 5;
    const int lane = tid & 31;
    const int warp_m = wid & 3;    // 32-row group
    const int warp_n = wid >> 2;   // 64-col group
    const int m0 = blockIdx.x * BM;

    // ---- issue the ENTIRE B load (64KB); gather hides it ----
    {
        uint32_t b_base = (uint32_t)__cvta_generic_to_shared(Bsm);
        const int c8 = (tid & 15) * 8;
        const int r0 = tid >> 4;
        #pragma unroll
        for (int it = 0; it < 16; it++) {
            int row = r0 + it * 16;
            cp_async16(b_base + (row * LDB + c8) * 2,
                       &g_wt[(size_t)row * D + c8]);
        }
        CP_COMMIT();
    }

    // ---- bias replica tile (fp32) ----
    for (int s = tid; s < 16 * LDBI; s += 256) {
        int c = s % LDBI;
        Bias[s] = (c < 128) ? (bl[c] + br[c]) : 0.f;
    }

    // ---- phase 1: gather agg rows into As, 2-node interleaved (fp32 -> fp16) ----
    {
        const int base_row = wid * 16;
        #pragma unroll
        for (int p = 0; p < 8; p++) {
            int row0 = base_row + p * 2;
            int n0 = m0 + row0;
            int n1 = n0 + 1;
            float4 a0 = make_float4(0.f, 0.f, 0.f, 0.f);
            float4 a1 = a0;
            int deg0 = 0, deg1 = 0;
            const uint2* bk0 = &g_bucket[0];
            const uint2* bk1 = bk0;
            if (n0 < NN) {
                deg0 = __ldg(&g_cnt[n0]);
                bk0  = &g_bucket[(size_t)n0 * CAP];
            }
            if (n1 < NN) {
                deg1 = __ldg(&g_cnt[n1]);
                bk1  = &g_bucket[(size_t)n1 * CAP];
            }
            // self-clean counters for next graph replay
            if (lane == 0) {
                if (n0 < NN) g_cnt[n0] = 0;
                if (n1 < NN) g_cnt[n1] = 0;
            }
            int mx = max(deg0, deg1);
            for (int j = 0; j < mx; j++) {
                uint2 e0, e1;
                if (j < deg0) e0 = __ldg(&bk0[j]);
                if (j < deg1) e1 = __ldg(&bk1[j]);
                if (j < deg0) {
                    float w = __uint_as_float(e0.y);
                    float4 v = *(const float4*)&x[(size_t)e0.x * D + lane * 4];
                    a0.x += w * v.x; a0.y += w * v.y;
                    a0.z += w * v.z; a0.w += w * v.w;
                }
                if (j < deg1) {
                    float w = __uint_as_float(e1.y);
                    float4 v = *(const float4*)&x[(size_t)e1.x * D + lane * 4];
                    a1.x += w * v.x; a1.y += w * v.y;
                    a1.z += w * v.z; a1.w += w * v.w;
                }
            }
            __half2* d0 = (__half2*)&As[row0][lane * 4];
            d0[0] = __floats2half2_rn(a0.x, a0.y);
            d0[1] = __floats2half2_rn(a0.z, a0.w);
            __half2* d1 = (__half2*)&As[row0 + 1][lane * 4];
            d1[0] = __floats2half2_rn(a1.x, a1.y);
            d1[1] = __floats2half2_rn(a1.z, a1.w);
        }
    }
    CP_WAIT(0);          // B resident
    __syncthreads();     // As + B + Bias visible

    // ---- init accumulators from bias ----
    wmma::fragment<wmma::accumulator, 16, 16, 16, float> acc[2][4];
    #pragma unroll
    for (int i = 0; i < 2; i++)
        #pragma unroll
        for (int j = 0; j < 4; j++)
            wmma::load_matrix_sync(acc[i][j], &Bias[warp_n * 64 + j * 16], LDBI,
                                   wmma::mem_row_major);

    // ---- GEMM over one K-half: no barriers, no waits ----
    auto gemm_half = [&](int kbase) {
        #pragma unroll
        for (int kc = 0; kc < 8; kc++) {
            wmma::fragment<wmma::matrix_a, 16, 16, 16, __half, wmma::row_major> af[2];
            #pragma unroll
            for (int i = 0; i < 2; i++)
                wmma::load_matrix_sync(af[i], &As[warp_m * 32 + i * 16][kc * 16], LDA);
            #pragma unroll
            for (int j = 0; j < 4; j++) {
                wmma::fragment<wmma::matrix_b, 16, 16, 16, __half, wmma::row_major> bf;
                wmma::load_matrix_sync(bf,
                    &Bsm[(size_t)(kbase + kc * 16) * LDB + warp_n * 64 + j * 16], LDB);
                #pragma unroll
                for (int i = 0; i < 2; i++)
                    wmma::mma_sync(acc[i][j], af[i], bf, acc[i][j]);
            }
        }
    };

    // ---- phase 2: agg @ Wl ----
    gemm_half(0);

    // ---- phase 3: overwrite As with this CTA's x rows (fp16) ----
    __syncthreads();
    #pragma unroll
    for (int it = 0; it < 8; it++) {
        int slot = tid + it * 256;        // 0..2047
        int row = slot >> 4;              // 0..127
        int c8  = (slot & 15) * 8;        // 0..120
        int gr = m0 + row;
        float4 v0 = make_float4(0.f, 0.f, 0.f, 0.f), v1 = v0;
        if (gr < NN) {
            v0 = *(const float4*)&x[(size_t)gr * D + c8];
            v1 = *(const float4*)&x[(size_t)gr * D + c8 + 4];
        }
        __half2 h[4];
        h[0] = __floats2half2_rn(v0.x, v0.y);
        h[1] = __floats2half2_rn(v0.z, v0.w);
        h[2] = __floats2half2_rn(v1.x, v1.y);
        h[3] = __floats2half2_rn(v1.z, v1.w);
        *(uint4*)&As[row][c8] = *(uint4*)h;
    }
    __syncthreads();

    // ---- phase 4: x @ Wr ----
    gemm_half(128);

    // ---- epilogue (NN % 16 == 0 -> tiles fully in or out) ----
    #pragma unroll
    for (int i = 0; i < 2; i++) {
        int row0 = m0 + warp_m * 32 + i * 16;
        if (row0 >= NN) continue;
        #pragma unroll
        for (int j = 0; j < 4; j++) {
            int col0 = warp_n * 64 + j * 16;
            wmma::store_matrix_sync(&out[(size_t)row0 * D + col0], acc[i][j], D,
                                    wmma::mem_row_major);
        }
    }
}

// ---------------- launch ----------------
extern "C" void kernel_launch(void* const* d_in, const int* in_sizes, int n_in,
                              void* d_out, int out_size)
{
    const float* x    = (const float*)d_in[0];
    const int*   esrc = (const int*)  d_in[1];
    const int*   edst = (const int*)  d_in[2];
    const float* ew   = (const float*)d_in[3];
    const float* wl   = (const float*)d_in[4];
    const float* bl   = (const float*)d_in[5];
    const float* wr   = (const float*)d_in[6];
    const float* br   = (const float*)d_in[7];
    float* out = (float*)d_out;

    static bool attr_set = false;
    if (!attr_set) {
        cudaFuncSetAttribute(fused_kernel,
                             cudaFuncAttributeMaxDynamicSharedMemorySize, SM_BYTES);
        attr_set = true;
    }

    prep_kernel<<<64, 256>>>(wl, wr);
    scatter_kernel<<<(NE + 255) / 256, 256>>>(esrc, edst, ew);
    fused_kernel<<<(NN + BM - 1) / BM, 256, SM_BYTES>>>(x, bl, br, out);
}

// round 13
// speedup vs baseline: 1.4144x; 1.3986x over previous
#include <cuda_runtime.h>
#include <cuda_fp16.h>
#include <mma.h>
#include <cstdint>

using namespace nvcuda;

#define NN 100000
#define NE 600000
#define D  128
#define CAP 64

// ---------------- device scratch ----------------
__device__ int    g_cnt[NN];
__device__ uint2  g_bucket[(size_t)NN * CAP];   // (src, weight_bits)
__device__ __half g_wt[2 * D * D];              // fp16 [Wl ; Wr]  (K-row major [256][128])

// ---------------- cp.async helpers ----------------
__device__ __forceinline__ void cp_async16(uint32_t dst, const void* src) {
    asm volatile("cp.async.cg.shared.global [%0], [%1], 16;"
                 :: "r"(dst), "l"(src) : "memory");
}
#define CP_COMMIT() asm volatile("cp.async.commit_group;" ::: "memory")
#define CP_WAIT(n)  asm volatile("cp.async.wait_group %0;" :: "n"(n) : "memory")

// ---------------- prep: zero counters + convert weights to fp16 ----------------
__global__ void __launch_bounds__(256) prep_kernel(
    const float* __restrict__ wl, const float* __restrict__ wr)
{
    int i = blockIdx.x * 256 + threadIdx.x;
    if (i < NN) g_cnt[i] = 0;
    if (i < D * D) {
        g_wt[i]         = __float2half_rn(wl[i]);
        g_wt[D * D + i] = __float2half_rn(wr[i]);
    }
}

// ---------------- scatter edges into buckets ----------------
__global__ void __launch_bounds__(256) scatter_kernel(
    const int* __restrict__ esrc,
    const int* __restrict__ edst,
    const float* __restrict__ ew)
{
    int e = blockIdx.x * 256 + threadIdx.x;
    if (e >= NE) return;
    int s = __ldg(&esrc[e]);
    int d = __ldg(&edst[e]);
    float w = __ldg(&ew[e]);
    int pos = atomicAdd(&g_cnt[d], 1);
    g_bucket[(size_t)d * CAP + pos] = make_uint2((unsigned)s, __float_as_uint(w));
}

// ---------------- fused gather + dual fp16 GEMM (B smem-resident) -------------
// out[tile] = agg(tile) @ Wl + x(tile) @ Wr + (bl+br)
#define BM 128
#define LDA 136     // halves
#define LDB 136     // halves
#define LDBI 136    // floats

// smem byte offsets
#define OFF_AS   0
#define OFF_B    (BM * LDA * 2)                      // 34816
#define OFF_BIAS (OFF_B + 256 * LDB * 2)             // +69632 = 104448
#define SM_BYTES (OFF_BIAS + 16 * LDBI * 4)          // +8704  = 113152

__global__ void __launch_bounds__(256, 2) fused_kernel(
    const float* __restrict__ x,
    const float* __restrict__ bl,
    const float* __restrict__ br,
    float* __restrict__ out)
{
    extern __shared__ char smraw[];
    __half (*As)[LDA] = (__half(*)[LDA])(smraw + OFF_AS);
    __half* Bsm  = (__half*)(smraw + OFF_B);     // [256][LDB]
    float*  Bias = (float*) (smraw + OFF_BIAS);  // [16][LDBI]

    const int tid = threadIdx.x;
    const int wid = tid >> 5;
    const int lane = tid & 31;
    const int warp_m = wid & 3;    // 32-row group
    const int warp_n = wid >> 2;   // 64-col group
    const int m0 = blockIdx.x * BM;

    // ---- issue the ENTIRE B load (64KB); gather hides it ----
    {
        uint32_t b_base = (uint32_t)__cvta_generic_to_shared(Bsm);
        const int c8 = (tid & 15) * 8;
        const int r0 = tid >> 4;
        #pragma unroll
        for (int it = 0; it < 16; it++) {
            int row = r0 + it * 16;
            cp_async16(b_base + (row * LDB + c8) * 2,
                       &g_wt[(size_t)row * D + c8]);
        }
        CP_COMMIT();
    }

    // ---- bias replica tile (fp32) ----
    for (int s = tid; s < 16 * LDBI; s += 256) {
        int c = s % LDBI;
        Bias[s] = (c < 128) ? (bl[c] + br[c]) : 0.f;
    }

    // ---- phase 1: gather agg rows into As (warp-parallel bucket + shfl bcast) ----
    {
        const int node_row = wid * 16;
        for (int i = 0; i < 16; i++) {
            int row = node_row + i;
            int n = m0 + row;
            float4 a = make_float4(0.f, 0.f, 0.f, 0.f);
            if (n < NN) {
                int deg = __ldg(&g_cnt[n]);
                const uint2* bk = &g_bucket[(size_t)n * CAP];
                // one parallel load fetches entries 0..min(deg,32)-1
                uint2 my_e = make_uint2(0u, 0u);
                if (lane < deg) my_e = __ldg(&bk[lane]);
                int nf = min(deg, 32);
                int j = 0;
                // 4-way unrolled: 4 independent x-row loads in flight
                for (; j + 4 <= nf; j += 4) {
                    unsigned s0 = __shfl_sync(0xffffffffu, my_e.x, j);
                    unsigned w0 = __shfl_sync(0xffffffffu, my_e.y, j);
                    unsigned s1 = __shfl_sync(0xffffffffu, my_e.x, j + 1);
                    unsigned w1 = __shfl_sync(0xffffffffu, my_e.y, j + 1);
                    unsigned s2 = __shfl_sync(0xffffffffu, my_e.x, j + 2);
                    unsigned w2 = __shfl_sync(0xffffffffu, my_e.y, j + 2);
                    unsigned s3 = __shfl_sync(0xffffffffu, my_e.x, j + 3);
                    unsigned w3 = __shfl_sync(0xffffffffu, my_e.y, j + 3);
                    float4 v0 = *(const float4*)&x[(size_t)s0 * D + lane * 4];
                    float4 v1 = *(const float4*)&x[(size_t)s1 * D + lane * 4];
                    float4 v2 = *(const float4*)&x[(size_t)s2 * D + lane * 4];
                    float4 v3 = *(const float4*)&x[(size_t)s3 * D + lane * 4];
                    float f0 = __uint_as_float(w0), f1 = __uint_as_float(w1);
                    float f2 = __uint_as_float(w2), f3 = __uint_as_float(w3);
                    a.x += f0 * v0.x; a.y += f0 * v0.y; a.z += f0 * v0.z; a.w += f0 * v0.w;
                    a.x += f1 * v1.x; a.y += f1 * v1.y; a.z += f1 * v1.z; a.w += f1 * v1.w;
                    a.x += f2 * v2.x; a.y += f2 * v2.y; a.z += f2 * v2.z; a.w += f2 * v2.w;
                    a.x += f3 * v3.x; a.y += f3 * v3.y; a.z += f3 * v3.z; a.w += f3 * v3.w;
                }
                for (; j < nf; j++) {
                    unsigned s0 = __shfl_sync(0xffffffffu, my_e.x, j);
                    unsigned w0 = __shfl_sync(0xffffffffu, my_e.y, j);
                    float f0 = __uint_as_float(w0);
                    float4 v0 = *(const float4*)&x[(size_t)s0 * D + lane * 4];
                    a.x += f0 * v0.x; a.y += f0 * v0.y; a.z += f0 * v0.z; a.w += f0 * v0.w;
                }
                // rare tail: deg > 32
                for (int t = 32; t < deg; t++) {
                    uint2 e = __ldg(&bk[t]);
                    float w = __uint_as_float(e.y);
                    float4 v = *(const float4*)&x[(size_t)e.x * D + lane * 4];
                    a.x += w * v.x; a.y += w * v.y; a.z += w * v.z; a.w += w * v.w;
                }
            }
            __half2* dst = (__half2*)&As[row][lane * 4];
            dst[0] = __floats2half2_rn(a.x, a.y);
            dst[1] = __floats2half2_rn(a.z, a.w);
        }
    }
    CP_WAIT(0);          // B resident
    __syncthreads();     // As + B + Bias visible

    // ---- init accumulators from bias ----
    wmma::fragment<wmma::accumulator, 16, 16, 16, float> acc[2][4];
    #pragma unroll
    for (int i = 0; i < 2; i++)
        #pragma unroll
        for (int j = 0; j < 4; j++)
            wmma::load_matrix_sync(acc[i][j], &Bias[warp_n * 64 + j * 16], LDBI,
                                   wmma::mem_row_major);

    // ---- GEMM over one K-half: no barriers, no waits ----
    auto gemm_half = [&](int kbase) {
        #pragma unroll
        for (int kc = 0; kc < 8; kc++) {
            wmma::fragment<wmma::matrix_a, 16, 16, 16, __half, wmma::row_major> af[2];
            #pragma unroll
            for (int i = 0; i < 2; i++)
                wmma::load_matrix_sync(af[i], &As[warp_m * 32 + i * 16][kc * 16], LDA);
            #pragma unroll
            for (int j = 0; j < 4; j++) {
                wmma::fragment<wmma::matrix_b, 16, 16, 16, __half, wmma::row_major> bf;
                wmma::load_matrix_sync(bf,
                    &Bsm[(size_t)(kbase + kc * 16) * LDB + warp_n * 64 + j * 16], LDB);
                #pragma unroll
                for (int i = 0; i < 2; i++)
                    wmma::mma_sync(acc[i][j], af[i], bf, acc[i][j]);
            }
        }
    };

    // ---- phase 2: agg @ Wl ----
    gemm_half(0);

    // ---- phase 3: overwrite As with this CTA's x rows (fp16) ----
    __syncthreads();
    #pragma unroll
    for (int it = 0; it < 8; it++) {
        int slot = tid + it * 256;        // 0..2047
        int row = slot >> 4;              // 0..127
        int c8  = (slot & 15) * 8;        // 0..120
        int gr = m0 + row;
        float4 v0 = make_float4(0.f, 0.f, 0.f, 0.f), v1 = v0;
        if (gr < NN) {
            v0 = *(const float4*)&x[(size_t)gr * D + c8];
            v1 = *(const float4*)&x[(size_t)gr * D + c8 + 4];
        }
        __half2 h[4];
        h[0] = __floats2half2_rn(v0.x, v0.y);
        h[1] = __floats2half2_rn(v0.z, v0.w);
        h[2] = __floats2half2_rn(v1.x, v1.y);
        h[3] = __floats2half2_rn(v1.z, v1.w);
        *(uint4*)&As[row][c8] = *(uint4*)h;
    }
    __syncthreads();

    // ---- phase 4: x @ Wr ----
    gemm_half(128);

    // ---- epilogue (NN % 16 == 0 -> tiles fully in or out) ----
    #pragma unroll
    for (int i = 0; i < 2; i++) {
        int row0 = m0 + warp_m * 32 + i * 16;
        if (row0 >= NN) continue;
        #pragma unroll
        for (int j = 0; j < 4; j++) {
            int col0 = warp_n * 64 + j * 16;
            wmma::store_matrix_sync(&out[(size_t)row0 * D + col0], acc[i][j], D,
                                    wmma::mem_row_major);
        }
    }
}

// ---------------- launch ----------------
extern "C" void kernel_launch(void* const* d_in, const int* in_sizes, int n_in,
                              void* d_out, int out_size)
{
    const float* x    = (const float*)d_in[0];
    const int*   esrc = (const int*)  d_in[1];
    const int*   edst = (const int*)  d_in[2];
    const float* ew   = (const float*)d_in[3];
    const float* wl   = (const float*)d_in[4];
    const float* bl   = (const float*)d_in[5];
    const float* wr   = (const float*)d_in[6];
    const float* br   = (const float*)d_in[7];
    float* out = (float*)d_out;

    static bool attr_set = false;
    if (!attr_set) {
        cudaFuncSetAttribute(fused_kernel,
                             cudaFuncAttributeMaxDynamicSharedMemorySize, SM_BYTES);
        attr_set = true;
    }

    prep_kernel<<<(NN + 255) / 256, 256>>>(wl, wr);
    scatter_kernel<<<(NE + 255) / 256, 256>>>(esrc, edst, ew);
    fused_kernel<<<(NN + BM - 1) / BM, 256, SM_BYTES>>>(x, bl, br, out);
}